// round 13
// baseline (speedup 1.0000x reference)
#include <cuda_runtime.h>
#include <math.h>

#define BB 4
#define NP 20000
#define CC 256
#define VV 300
#define SS 1024
#define EPSV 1e-5f

// ---- output layout (flattened tuple, float32) ----
#define OFF_GRASP   0
#define OFF_OBJ     80000
#define OFF_GXYZ    160000
#define OFF_INDS    172288
#define OFF_GFEAT   176384
#define OFF_FP2     1224960
#define OFF_VS      1229056
#define OFF_TVI     2457856
#define OFF_TVS     2461952
#define OFF_VPX     2466048
#define OFF_ROT     2478336

// ---- device scratch (static: no allocations allowed) ----
__device__ float d_w1Tgh[CC*CC];
__device__ float d_w1T[CC*CC];
__device__ float d_w2T[CC*VV];
__device__ float d_w3T[VV*VV];
__device__ float d_s1gh[CC], d_c1gh[CC];
__device__ float d_sA[CC],  d_cA[CC];
__device__ float d_sB[VV],  d_cB[VV];
__device__ float d_graspness[BB*NP];
__device__ unsigned char d_maskg[BB*NP];
__device__ int   d_inds[BB*SS];
__device__ float d_f1[BB*CC*SS];
__device__ float d_f2[BB*VV*SS];
__device__ float d_tpl[VV*3];
__device__ float d_fdist[BB*NP];   // FPS fallback scratch

#define FMA2(acc, f2, w2) asm("fma.rn.f32x2 %0, %1, %2, %0;" : "+l"(acc) : "l"(f2), "l"(w2))

__device__ __forceinline__ unsigned long long pack2(float w){
    unsigned long long r;
    unsigned u = __float_as_uint(w);
    asm("mov.b64 %0, {%1, %1};" : "=l"(r) : "r"(u));
    return r;
}
__device__ __forceinline__ void unpack2(unsigned long long p, float& lo, float& hi){
    unsigned a, b;
    asm("mov.b64 {%0, %1}, %2;" : "=r"(a), "=r"(b) : "l"(p));
    lo = __uint_as_float(a); hi = __uint_as_float(b);
}

// =====================================================================
// prep (single launch): templates + BN constants + all 4 transposes
// =====================================================================
__global__ void prep_all(const float* gh_w1, const float* w1, const float* w2, const float* w3,
                         const float* gh_b1,const float* gh_g1,const float* gh_be1,
                         const float* gh_m1,const float* gh_v1,
                         const float* b1,const float* g1,const float* be1,
                         const float* m1,const float* v1,
                         const float* b2,const float* g2,const float* be2,
                         const float* m2,const float* v2){
    if (blockIdx.x == 0){
        for (int t = threadIdx.x; t < VV; t += blockDim.x){
            if (t < CC){
                float s = gh_g1[t] / sqrtf(gh_v1[t] + EPSV);
                d_s1gh[t] = s;
                d_c1gh[t] = (gh_b1[t] - gh_m1[t]) * s + gh_be1[t];
                float sa = g1[t] / sqrtf(v1[t] + EPSV);
                d_sA[t] = sa;
                d_cA[t] = (b1[t] - m1[t]) * sa + be1[t];
            }
            float sb = g2[t] / sqrtf(v2[t] + EPSV);
            d_sB[t] = sb;
            d_cB[t] = (b2[t] - m2[t]) * sb + be2[t];
            double phi = (sqrt(5.0) - 1.0) * 0.5;
            double zi  = (2.0*t + 1.0) / (double)VV - 1.0;
            double r2  = 1.0 - zi*zi; if (r2 < 0.0) r2 = 0.0;
            double ri  = sqrt(r2);
            double ang = 2.0 * 3.141592653589793 * (double)t * phi;
            d_tpl[t*3+0] = (float)(ri * cos(ang));
            d_tpl[t*3+1] = (float)(ri * sin(ang));
            d_tpl[t*3+2] = (float)zi;
        }
        return;
    }
    int e = (blockIdx.x - 1) * blockDim.x + threadIdx.x;
    const int N1 = CC*CC, N2 = CC*CC, N3 = VV*CC, N4 = VV*VV;
    if (e < N1){
        int o = e / CC, k = e - o*CC; d_w1Tgh[k*CC + o] = gh_w1[e]; return;
    }
    e -= N1;
    if (e < N2){
        int o = e / CC, k = e - o*CC; d_w1T[k*CC + o] = w1[e]; return;
    }
    e -= N2;
    if (e < N3){
        int o = e / CC, k = e - o*CC; d_w2T[k*VV + o] = w2[e]; return;
    }
    e -= N3;
    if (e < N4){
        int o = e / VV, k = e - o*VV; d_w3T[k*VV + o] = w3[e]; return;
    }
}

// =====================================================================
// Kernel 1: graspness head. Register-tiled GEMM (R11-proven).
// =====================================================================
__global__ __launch_bounds__(256,2)
void k1_head(const float* __restrict__ F, const float* __restrict__ w2h,
             const float* __restrict__ b2h, float* __restrict__ out){
    __shared__ __align__(16) float ws[32][256];
    __shared__ __align__(16) float fs[32][64];
    __shared__ float part[3][64][2];
    __shared__ float proj[3][64];

    const int tid = threadIdx.x;
    const int b   = blockIdx.y;
    const int n0  = blockIdx.x * 64;
    const int og  = tid & 63;
    const int o0  = og * 4;
    const int pg  = tid >> 6;
    const int p0  = pg * 16;

    unsigned long long acc2[4][8];
#pragma unroll
    for (int o = 0; o < 4; o++)
#pragma unroll
        for (int i = 0; i < 8; i++) acc2[o][i] = 0ULL;

    const float* Fb = F + (size_t)b * CC * NP;

    for (int kc = 0; kc < 8; kc++){
#pragma unroll
        for (int r = 0; r < 8; r++){
            int e = r*256 + tid;
            int k = e >> 6, o4 = e & 63;
            ((float4*)ws[k])[o4] =
                ((const float4*)(d_w1Tgh + (size_t)(kc*32 + k)*256))[o4];
        }
#pragma unroll
        for (int r = 0; r < 8; r++){
            int e = r*256 + tid;
            int k = e >> 6, t = e & 63;
            int n = n0 + t;
            fs[k][t] = (n < NP) ? Fb[(size_t)(kc*32 + k)*NP + n] : 0.f;
        }
        __syncthreads();
#pragma unroll
        for (int k = 0; k < 32; k++){
            float4 w4 = *(const float4*)&ws[k][o0];
            unsigned long long w2a = pack2(w4.x), w2b = pack2(w4.y),
                               w2c = pack2(w4.z), w2d = pack2(w4.w);
            const ulonglong2* fr = (const ulonglong2*)&fs[k][p0];
            ulonglong2 f0 = fr[0], f1 = fr[1], f2 = fr[2], f3 = fr[3];
            unsigned long long fp[8] = {f0.x, f0.y, f1.x, f1.y,
                                        f2.x, f2.y, f3.x, f3.y};
#pragma unroll
            for (int i = 0; i < 8; i++){
                FMA2(acc2[0][i], fp[i], w2a);
                FMA2(acc2[1][i], fp[i], w2b);
                FMA2(acc2[2][i], fp[i], w2c);
                FMA2(acc2[3][i], fp[i], w2d);
            }
        }
        __syncthreads();
    }

    float s1v[4], c1v[4], pw0[4], pw1[4], pw2[4];
#pragma unroll
    for (int o = 0; o < 4; o++){
        s1v[o] = d_s1gh[o0+o]; c1v[o] = d_c1gh[o0+o];
        pw0[o] = w2h[o0+o]; pw1[o] = w2h[256+o0+o]; pw2[o] = w2h[512+o0+o];
    }
    const int lane = tid & 31, wid = tid >> 5;

#pragma unroll
    for (int pp = 0; pp < 8; pp++){
        float q0[2] = {0.f,0.f}, q1[2] = {0.f,0.f}, q2[2] = {0.f,0.f};
#pragma unroll
        for (int o = 0; o < 4; o++){
            float lo, hi; unpack2(acc2[o][pp], lo, hi);
            float h0 = fmaxf(lo*s1v[o] + c1v[o], 0.f);
            float h1 = fmaxf(hi*s1v[o] + c1v[o], 0.f);
            q0[0] += pw0[o]*h0; q1[0] += pw1[o]*h0; q2[0] += pw2[o]*h0;
            q0[1] += pw0[o]*h1; q1[1] += pw1[o]*h1; q2[1] += pw2[o]*h1;
        }
#pragma unroll
        for (int h = 0; h < 2; h++){
            float a = q0[h], c = q1[h], d = q2[h];
#pragma unroll
            for (int off = 16; off > 0; off >>= 1){
                a += __shfl_down_sync(0xffffffffu, a, off);
                c += __shfl_down_sync(0xffffffffu, c, off);
                d += __shfl_down_sync(0xffffffffu, d, off);
            }
            if (lane == 0){
                int p = p0 + 2*pp + h;
                part[0][p][wid & 1] = a;
                part[1][p][wid & 1] = c;
                part[2][p][wid & 1] = d;
            }
        }
    }
    __syncthreads();
    if (tid < 192){
        int j = tid >> 6, p = tid & 63;
        proj[j][p] = part[j][p][0] + part[j][p][1];
    }
    __syncthreads();
    if (tid < 64){
        int n = n0 + tid;
        if (n < NP){
            float g  = proj[2][tid] + b2h[2];
            float o0v = proj[0][tid] + b2h[0];
            float o1v = proj[1][tid] + b2h[1];
            bool obj = (o1v > o0v);
            size_t idx = (size_t)b * NP + n;
            d_graspness[idx] = g;
            out[OFF_GRASP + idx] = g;
            out[OFF_OBJ   + idx] = obj ? 1.f : 0.f;
            d_maskg[idx] = ((g > 0.1f) && obj) ? 1 : 0;
        }
    }
}

// =====================================================================
// Kernel 2: masked FPS (R12-proven): register distances via template
// KPT dispatch, single barrier/iter, REDUX-only reduction.
// =====================================================================
#define CAP 12288
#define FPS_SMEM (CAP*8 + CAP*4 + CAP*2)

template<int KPT>
__device__ __forceinline__ void fps_smem_loop(
    const float2* __restrict__ sxy, const float* __restrict__ szz,
    const unsigned short* __restrict__ sidx, int M, int b,
    unsigned (&sval)[2][32], int (&sjj)[2][32],
    int tid, int lane, int wid)
{
    float dist[KPT];
#pragma unroll
    for (int k = 0; k < KPT; k++) dist[k] = 1e10f;

    int w = 0;
    int pb = 0;
    for (int it = 0; it < SS; it++){
        if (tid == 0) d_inds[b*SS + it] = (int)sidx[w];
        float2 cxy = sxy[w];
        float  cz  = szz[w];

        unsigned bvb = 0u; int bj = 0x7fffffff;
#pragma unroll
        for (int k = 0; k < KPT; k++){
            int j = tid + (k << 10);
            if (j < M){
                float2 p2 = sxy[j];
                float dx = p2.x - cxy.x, dy = p2.y - cxy.y, dz = szz[j] - cz;
                float d = fminf(dist[k], fmaf(dx, dx, fmaf(dy, dy, dz*dz)));
                dist[k] = d;
                unsigned db = __float_as_uint(d);
                if (db > bvb){ bvb = db; bj = j; }
            }
        }
        unsigned wm = __reduce_max_sync(0xffffffffu, bvb);
        unsigned cand = (bvb == wm) ? (unsigned)bj : 0x7fffffffu;
        cand = __reduce_min_sync(0xffffffffu, cand);
        if (lane == 0){ sval[pb][wid] = wm; sjj[pb][wid] = (int)cand; }
        __syncthreads();
        unsigned mv = sval[pb][lane];
        unsigned gm = __reduce_max_sync(0xffffffffu, mv);
        unsigned c2 = (mv == gm) ? (unsigned)sjj[pb][lane] : 0x7fffffffu;
        c2 = __reduce_min_sync(0xffffffffu, c2);
        w = (int)c2;
        pb ^= 1;
    }
}

__global__ __launch_bounds__(1024,1)
void fps_kernel(const float* __restrict__ xyz){
    extern __shared__ char smemc[];
    float2*          sxy  = (float2*)smemc;
    float*           szz  = (float*)(smemc + (size_t)CAP*8);
    unsigned short*  sidx = (unsigned short*)(smemc + (size_t)CAP*12);

    __shared__ unsigned sval[2][32];
    __shared__ int      sjj[2][32];
    __shared__ int      warp_i[32];
    __shared__ int scur;
    __shared__ int sM;

    const int b = blockIdx.x, tid = threadIdx.x;
    const int lane = tid & 31, wid = tid >> 5;
    const float* X = xyz + (size_t)b * NP * 3;
    const unsigned char* mk = d_maskg + (size_t)b * NP;

    int i0 = tid * 20;
    int cnt = 0;
    if (i0 < NP){
        int ie = min(i0 + 20, NP);
        for (int i = i0; i < ie; i++) cnt += mk[i] ? 1 : 0;
    }
    int x = cnt;
#pragma unroll
    for (int off = 1; off < 32; off <<= 1){
        int y = __shfl_up_sync(0xffffffffu, x, off);
        if (lane >= off) x += y;
    }
    if (lane == 31) warp_i[wid] = x;
    __syncthreads();
    if (wid == 0){
        int s = warp_i[lane];
#pragma unroll
        for (int off = 1; off < 32; off <<= 1){
            int y = __shfl_up_sync(0xffffffffu, s, off);
            if (lane >= off) s += y;
        }
        warp_i[lane] = s;
        if (lane == 31) sM = s;
    }
    __syncthreads();
    const int M = sM;
    int base = ((wid > 0) ? warp_i[wid-1] : 0) + (x - cnt);
    __syncthreads();

    if (M == 0){
        for (int it = tid; it < SS; it += 1024) d_inds[b*SS + it] = 0;
        return;
    }

    if (M <= CAP){
        if (i0 < NP){
            int ie = min(i0 + 20, NP);
            int p = base;
            for (int i = i0; i < ie; i++){
                if (mk[i]){
                    sxy[p] = make_float2(X[i*3+0], X[i*3+1]);
                    szz[p] = X[i*3+2];
                    sidx[p] = (unsigned short)i;
                    p++;
                }
            }
        }
        __syncthreads();

        int kmax = (M + 1023) >> 10;
        switch (kmax){
        case 1:  fps_smem_loop<1> (sxy,szz,sidx,M,b,sval,sjj,tid,lane,wid); break;
        case 2:  fps_smem_loop<2> (sxy,szz,sidx,M,b,sval,sjj,tid,lane,wid); break;
        case 3:  fps_smem_loop<3> (sxy,szz,sidx,M,b,sval,sjj,tid,lane,wid); break;
        case 4:  fps_smem_loop<4> (sxy,szz,sidx,M,b,sval,sjj,tid,lane,wid); break;
        case 5:  fps_smem_loop<5> (sxy,szz,sidx,M,b,sval,sjj,tid,lane,wid); break;
        case 6:  fps_smem_loop<6> (sxy,szz,sidx,M,b,sval,sjj,tid,lane,wid); break;
        case 7:  fps_smem_loop<7> (sxy,szz,sidx,M,b,sval,sjj,tid,lane,wid); break;
        case 8:  fps_smem_loop<8> (sxy,szz,sidx,M,b,sval,sjj,tid,lane,wid); break;
        case 9:  fps_smem_loop<9> (sxy,szz,sidx,M,b,sval,sjj,tid,lane,wid); break;
        case 10: fps_smem_loop<10>(sxy,szz,sidx,M,b,sval,sjj,tid,lane,wid); break;
        case 11: fps_smem_loop<11>(sxy,szz,sidx,M,b,sval,sjj,tid,lane,wid); break;
        default: fps_smem_loop<12>(sxy,szz,sidx,M,b,sval,sjj,tid,lane,wid); break;
        }
    } else {
        float* fd = d_fdist + (size_t)b * NP;
        int startv = 0x7fffffff;
        for (int i = tid; i < NP; i += 1024){
            bool m = mk[i] != 0;
            fd[i] = m ? 1e10f : -1.f;
            if (m) startv = min(startv, i);
        }
        startv = (int)__reduce_min_sync(0xffffffffu, (unsigned)startv);
        if (lane == 0) warp_i[wid] = startv;
        __syncthreads();
        if (wid == 0){
            int s = (int)__reduce_min_sync(0xffffffffu, (unsigned)warp_i[lane]);
            if (lane == 0) scur = s;
        }
        __syncthreads();
        int cur = scur;
        __syncthreads();

        int pb = 0;
        for (int it = 0; it < SS; it++){
            if (tid == 0) d_inds[b*SS + it] = cur;
            float cx = X[cur*3+0], cy = X[cur*3+1], cz = X[cur*3+2];
            unsigned bvb = 0u; int bi = 0x7fffffff;
            for (int i = tid; i < NP; i += 1024){
                float d = fd[i];
                if (d >= 0.f){
                    float dx = X[i*3+0]-cx, dy = X[i*3+1]-cy, dz = X[i*3+2]-cz;
                    d = fminf(d, fmaf(dx,dx, fmaf(dy,dy, dz*dz)));
                    fd[i] = d;
                    unsigned db = __float_as_uint(d);
                    if (db > bvb || bi == 0x7fffffff){ bvb = db; bi = i; }
                }
            }
            unsigned wm = __reduce_max_sync(0xffffffffu, bvb);
            unsigned cand = (bvb == wm) ? (unsigned)bi : 0x7fffffffu;
            cand = __reduce_min_sync(0xffffffffu, cand);
            if (lane == 0){ sval[pb][wid] = wm; sjj[pb][wid] = (int)cand; }
            __syncthreads();
            unsigned mv = sval[pb][lane];
            unsigned gm = __reduce_max_sync(0xffffffffu, mv);
            unsigned c2 = (mv == gm) ? (unsigned)sjj[pb][lane] : 0x7fffffffu;
            c2 = __reduce_min_sync(0xffffffffu, c2);
            cur = (int)c2;
            pb ^= 1;
        }
    }
}

// =====================================================================
// gathers (output copies only; d_gf eliminated — mlp0 gathers inline)
// =====================================================================
__global__ void gather_small(const float* __restrict__ xyz, float* __restrict__ out){
    int g = blockIdx.x * blockDim.x + threadIdx.x;
    if (g >= BB*SS) return;
    int b = g >> 10;
    int idx = d_inds[g];
    out[OFF_INDS + g] = (float)idx;
    size_t p = (size_t)b * NP + idx;
    out[OFF_GXYZ + (size_t)g*3 + 0] = xyz[p*3 + 0];
    out[OFF_GXYZ + (size_t)g*3 + 1] = xyz[p*3 + 1];
    out[OFF_GXYZ + (size_t)g*3 + 2] = xyz[p*3 + 2];
    out[OFF_FP2 + g] = d_graspness[p];
}

__global__ void gather_feat_out(const float* __restrict__ F, float* __restrict__ out){
    int b = blockIdx.x, c = blockIdx.y, tid = threadIdx.x;
    const float* Fr = F + ((size_t)b*CC + c) * NP;
    float* g2p = out + OFF_GFEAT + ((size_t)b*CC + c) * SS;
#pragma unroll
    for (int r = 0; r < 4; r++){
        int s = r*256 + tid;
        int idx = d_inds[b*SS + s];
        g2p[s] = Fr[idx];
    }
}

// =====================================================================
// fused conv1x1(+bn+relu) layers over the 1024 samples (f32x2 math).
// layer 0 stages its input by gathering DIRECTLY from seed_features
// (indices cached in smem) -> no d_gf buffer, launchable right after fps.
// =====================================================================
__global__ void mlp_kernel(int layer, const float* __restrict__ Fsrc,
                           const float* __restrict__ b3, float* __restrict__ outbuf){
    __shared__ __align__(16) float fs[32][32];
    __shared__ float ws[32][320];
    __shared__ int sidxs[32];

    const int tid = threadIdx.x, nt = blockDim.x;
    const int b = blockIdx.y, s0 = blockIdx.x * 32;

    const float* in = (layer == 1) ? d_f1 : d_f2;
    const float* wT = (layer == 0) ? d_w1T : (layer == 1) ? d_w2T : d_w3T;
    const int K = (layer == 2) ? VV : CC;
    const int O = (layer == 0) ? CC : VV;

    if (layer == 0 && tid < 32) sidxs[tid] = d_inds[b*SS + s0 + tid];
    if (layer == 0) __syncthreads();

    unsigned long long acc2[16];
#pragma unroll
    for (int i = 0; i < 16; i++) acc2[i] = 0ULL;

    const float* inb = in + (size_t)b * K * SS;
    const float* Fb  = Fsrc + (size_t)b * CC * NP;
    for (int kc = 0; kc < K; kc += 32){
        int kk = min(32, K - kc);
        if (layer == 0){
            for (int e = tid; e < kk*32; e += nt){
                int k = e >> 5, t = e & 31;
                fs[k][t] = Fb[(size_t)(kc + k)*NP + sidxs[t]];
            }
        } else {
            for (int e = tid; e < kk*32; e += nt){
                int k = e >> 5, t = e & 31;
                fs[k][t] = inb[(size_t)(kc + k)*SS + s0 + t];
            }
        }
        for (int e = tid; e < kk*O; e += nt){
            int k = e / O, o = e - k*O;
            ws[k][o] = wT[(size_t)(kc + k)*O + o];
        }
        __syncthreads();
        if (tid < O){
            for (int k = 0; k < kk; k++){
                unsigned long long wp = pack2(ws[k][tid]);
                const ulonglong2* fr = reinterpret_cast<const ulonglong2*>(fs[k]);
#pragma unroll
                for (int i = 0; i < 8; i++){
                    ulonglong2 fp = fr[i];
                    FMA2(acc2[2*i+0], fp.x, wp);
                    FMA2(acc2[2*i+1], fp.y, wp);
                }
            }
        }
        __syncthreads();
    }

    if (tid < O){
        float accf[32];
#pragma unroll
        for (int i = 0; i < 16; i++) unpack2(acc2[i], accf[2*i], accf[2*i+1]);
        if (layer < 2){
            const float* scale = (layer == 0) ? d_sA : d_sB;
            const float* shift = (layer == 0) ? d_cA : d_cB;
            float sc = scale[tid], sh = shift[tid];
            float* ob = ((layer == 0) ? d_f1 : d_f2) + ((size_t)b*O + tid)*SS + s0;
#pragma unroll
            for (int t = 0; t < 32; t++) ob[t] = fmaxf(accf[t]*sc + sh, 0.f);
        } else {
            float sh = b3[tid];
            float* ob = outbuf + OFF_VS + ((size_t)(b*SS + s0))*VV + tid;
#pragma unroll
            for (int t = 0; t < 32; t++) ob[(size_t)t*VV] = accf[t] + sh;
        }
    }
}

// =====================================================================
// top view + rotation epilogue
// =====================================================================
__global__ void top_kernel(float* __restrict__ out){
    int g = blockIdx.x * blockDim.x + threadIdx.x;
    if (g >= BB*SS) return;
    const float* row = out + OFF_VS + (size_t)g * VV;
    float bv = row[0]; int bi = 0;
    for (int o = 1; o < VV; o++){
        float v = row[o];
        if (v > bv){ bv = v; bi = o; }
    }
    out[OFF_TVI + g] = (float)bi;
    out[OFF_TVS + g] = bv;
    float tx = d_tpl[bi*3+0], ty = d_tpl[bi*3+1], tz = d_tpl[bi*3+2];
    out[OFF_VPX + (size_t)g*3 + 0] = tx;
    out[OFF_VPX + (size_t)g*3 + 1] = ty;
    out[OFF_VPX + (size_t)g*3 + 2] = tz;

    float ax = -tx, ay = -ty, az = -tz;
    float byx = -ay, byy = ax, byz = 0.f;
    float ny = sqrtf(byx*byx + byy*byy);
    if (ny == 0.f){ byx = 0.f; byy = 1.f; byz = 0.f; }
    float nx = sqrtf(ax*ax + ay*ay + az*az);
    ax /= nx; ay /= nx; az /= nx;
    float ny2 = sqrtf(byx*byx + byy*byy + byz*byz);
    byx /= ny2; byy /= ny2; byz /= ny2;
    float czx = ay*byz - az*byy;
    float czy = az*byx - ax*byz;
    float czz = ax*byy - ay*byx;
    float* R = out + OFF_ROT + (size_t)g * 9;
    R[0] = ax; R[1] = byx; R[2] = czx;
    R[3] = ay; R[4] = byy; R[5] = czy;
    R[6] = az; R[7] = byz; R[8] = czz;
}

// =====================================================================
extern "C" void kernel_launch(void* const* d_in, const int* in_sizes, int n_in,
                              void* d_out, int out_size){
    const float* seed_xyz  = (const float*)d_in[0];
    const float* seed_feat = (const float*)d_in[1];
    const float* gh_w1 = (const float*)d_in[2];
    const float* gh_b1 = (const float*)d_in[3];
    const float* gh_g1 = (const float*)d_in[4];
    const float* gh_be1= (const float*)d_in[5];
    const float* gh_m1 = (const float*)d_in[6];
    const float* gh_v1 = (const float*)d_in[7];
    const float* gh_w2 = (const float*)d_in[8];
    const float* gh_b2 = (const float*)d_in[9];
    const float* w1  = (const float*)d_in[10];
    const float* b1  = (const float*)d_in[11];
    const float* g1  = (const float*)d_in[12];
    const float* be1 = (const float*)d_in[13];
    const float* m1  = (const float*)d_in[14];
    const float* v1  = (const float*)d_in[15];
    const float* w2  = (const float*)d_in[16];
    const float* b2  = (const float*)d_in[17];
    const float* g2  = (const float*)d_in[18];
    const float* be2 = (const float*)d_in[19];
    const float* m2  = (const float*)d_in[20];
    const float* v2  = (const float*)d_in[21];
    const float* w3  = (const float*)d_in[22];
    const float* b3  = (const float*)d_in[23];
    float* out = (float*)d_out;

    static bool attr_set = false;
    if (!attr_set){
        cudaFuncSetAttribute(fps_kernel, cudaFuncAttributeMaxDynamicSharedMemorySize, FPS_SMEM);
        attr_set = true;
    }

    const int total_tr = CC*CC + CC*CC + VV*CC + VV*VV;
    // position 1
    prep_all<<<1 + (total_tr + 255)/256, 256>>>(gh_w1, w1, w2, w3,
                            gh_b1, gh_g1, gh_be1, gh_m1, gh_v1,
                            b1, g1, be1, m1, v1,
                            b2, g2, be2, m2, v2);
    // position 2
    k1_head<<<dim3((NP + 63)/64, BB), 256>>>(seed_feat, gh_w2, gh_b2, out);
    // position 3
    fps_kernel<<<BB, 1024, FPS_SMEM>>>(seed_xyz);
    // position 4 (PROFILED): mlp layer 0 with inline gather
    mlp_kernel<<<dim3(SS/32, BB), 256>>>(0, seed_feat, b3, out);

    gather_small<<<(BB*SS + 255)/256, 256>>>(seed_xyz, out);
    gather_feat_out<<<dim3(BB, CC), 256>>>(seed_feat, out);

    mlp_kernel<<<dim3(SS/32, BB), 320>>>(1, seed_feat, b3, out);
    mlp_kernel<<<dim3(SS/32, BB), 320>>>(2, seed_feat, b3, out);

    top_kernel<<<(BB*SS + 255)/256, 256>>>(out);
}

// round 14
// speedup vs baseline: 1.3872x; 1.3872x over previous
#include <cuda_runtime.h>
#include <math.h>

#define BB 4
#define NP 20000
#define CC 256
#define VV 300
#define SS 1024
#define OPAD 320
#define EPSV 1e-5f

// ---- output layout (flattened tuple, float32) ----
#define OFF_GRASP   0
#define OFF_OBJ     80000
#define OFF_GXYZ    160000
#define OFF_INDS    172288
#define OFF_GFEAT   176384
#define OFF_FP2     1224960
#define OFF_VS      1229056
#define OFF_TVI     2457856
#define OFF_TVS     2461952
#define OFF_VPX     2466048
#define OFF_ROT     2478336

// ---- device scratch (static: no allocations allowed) ----
__device__ float d_w1Tgh[CC*CC];
__device__ float d_w1T[CC*CC];
__device__ float d_w2T[CC*OPAD];
__device__ float d_w3T[VV*OPAD];
__device__ float d_s1gh[CC], d_c1gh[CC];
__device__ float d_sA[CC],  d_cA[CC];
__device__ float d_sB[VV],  d_cB[VV];
__device__ float d_graspness[BB*NP];
__device__ unsigned char d_maskg[BB*NP];
__device__ int   d_inds[BB*SS];
__device__ float d_tpl[VV*3];
__device__ float d_fdist[BB*NP];   // FPS fallback scratch

#define FMA2(acc, f2, w2) asm("fma.rn.f32x2 %0, %1, %2, %0;" : "+l"(acc) : "l"(f2), "l"(w2))

__device__ __forceinline__ unsigned long long pack2(float w){
    unsigned long long r;
    unsigned u = __float_as_uint(w);
    asm("mov.b64 %0, {%1, %1};" : "=l"(r) : "r"(u));
    return r;
}
__device__ __forceinline__ void unpack2(unsigned long long p, float& lo, float& hi){
    unsigned a, b;
    asm("mov.b64 {%0, %1}, %2;" : "=r"(a), "=r"(b) : "l"(p));
    lo = __uint_as_float(a); hi = __uint_as_float(b);
}

// =====================================================================
// prep (single launch): templates + BN constants + all 4 transposes
// w2T/w3T stored [k][OPAD] with zero pad for o in [300,320).
// =====================================================================
__global__ void prep_all(const float* gh_w1, const float* w1, const float* w2, const float* w3,
                         const float* gh_b1,const float* gh_g1,const float* gh_be1,
                         const float* gh_m1,const float* gh_v1,
                         const float* b1,const float* g1,const float* be1,
                         const float* m1,const float* v1,
                         const float* b2,const float* g2,const float* be2,
                         const float* m2,const float* v2){
    if (blockIdx.x == 0){
        for (int t = threadIdx.x; t < VV; t += blockDim.x){
            if (t < CC){
                float s = gh_g1[t] / sqrtf(gh_v1[t] + EPSV);
                d_s1gh[t] = s;
                d_c1gh[t] = (gh_b1[t] - gh_m1[t]) * s + gh_be1[t];
                float sa = g1[t] / sqrtf(v1[t] + EPSV);
                d_sA[t] = sa;
                d_cA[t] = (b1[t] - m1[t]) * sa + be1[t];
            }
            float sb = g2[t] / sqrtf(v2[t] + EPSV);
            d_sB[t] = sb;
            d_cB[t] = (b2[t] - m2[t]) * sb + be2[t];
            double phi = (sqrt(5.0) - 1.0) * 0.5;
            double zi  = (2.0*t + 1.0) / (double)VV - 1.0;
            double r2  = 1.0 - zi*zi; if (r2 < 0.0) r2 = 0.0;
            double ri  = sqrt(r2);
            double ang = 2.0 * 3.141592653589793 * (double)t * phi;
            d_tpl[t*3+0] = (float)(ri * cos(ang));
            d_tpl[t*3+1] = (float)(ri * sin(ang));
            d_tpl[t*3+2] = (float)zi;
        }
        return;
    }
    int e = (blockIdx.x - 1) * blockDim.x + threadIdx.x;
    const int N1 = CC*CC, N2 = CC*CC, N3 = CC*OPAD, N4 = VV*OPAD;
    if (e < N1){
        int o = e / CC, k = e - o*CC; d_w1Tgh[k*CC + o] = gh_w1[e]; return;
    }
    e -= N1;
    if (e < N2){
        int o = e / CC, k = e - o*CC; d_w1T[k*CC + o] = w1[e]; return;
    }
    e -= N2;
    if (e < N3){
        int k = e / OPAD, o = e - k*OPAD;
        d_w2T[e] = (o < VV) ? w2[o*CC + k] : 0.f;
        return;
    }
    e -= N3;
    if (e < N4){
        int k = e / OPAD, o = e - k*OPAD;
        d_w3T[e] = (o < VV) ? w3[o*VV + k] : 0.f;
        return;
    }
}

// =====================================================================
// Kernel 1: graspness head. Register-tiled GEMM (R11-proven).
// =====================================================================
__global__ __launch_bounds__(256,2)
void k1_head(const float* __restrict__ F, const float* __restrict__ w2h,
             const float* __restrict__ b2h, float* __restrict__ out){
    __shared__ __align__(16) float ws[32][256];
    __shared__ __align__(16) float fs[32][64];
    __shared__ float part[3][64][2];
    __shared__ float proj[3][64];

    const int tid = threadIdx.x;
    const int b   = blockIdx.y;
    const int n0  = blockIdx.x * 64;
    const int og  = tid & 63;
    const int o0  = og * 4;
    const int pg  = tid >> 6;
    const int p0  = pg * 16;

    unsigned long long acc2[4][8];
#pragma unroll
    for (int o = 0; o < 4; o++)
#pragma unroll
        for (int i = 0; i < 8; i++) acc2[o][i] = 0ULL;

    const float* Fb = F + (size_t)b * CC * NP;

    for (int kc = 0; kc < 8; kc++){
#pragma unroll
        for (int r = 0; r < 8; r++){
            int e = r*256 + tid;
            int k = e >> 6, o4 = e & 63;
            ((float4*)ws[k])[o4] =
                ((const float4*)(d_w1Tgh + (size_t)(kc*32 + k)*256))[o4];
        }
#pragma unroll
        for (int r = 0; r < 8; r++){
            int e = r*256 + tid;
            int k = e >> 6, t = e & 63;
            int n = n0 + t;
            fs[k][t] = (n < NP) ? Fb[(size_t)(kc*32 + k)*NP + n] : 0.f;
        }
        __syncthreads();
#pragma unroll
        for (int k = 0; k < 32; k++){
            float4 w4 = *(const float4*)&ws[k][o0];
            unsigned long long w2a = pack2(w4.x), w2b = pack2(w4.y),
                               w2c = pack2(w4.z), w2d = pack2(w4.w);
            const ulonglong2* fr = (const ulonglong2*)&fs[k][p0];
            ulonglong2 f0 = fr[0], f1 = fr[1], f2 = fr[2], f3 = fr[3];
            unsigned long long fp[8] = {f0.x, f0.y, f1.x, f1.y,
                                        f2.x, f2.y, f3.x, f3.y};
#pragma unroll
            for (int i = 0; i < 8; i++){
                FMA2(acc2[0][i], fp[i], w2a);
                FMA2(acc2[1][i], fp[i], w2b);
                FMA2(acc2[2][i], fp[i], w2c);
                FMA2(acc2[3][i], fp[i], w2d);
            }
        }
        __syncthreads();
    }

    float s1v[4], c1v[4], pw0[4], pw1[4], pw2[4];
#pragma unroll
    for (int o = 0; o < 4; o++){
        s1v[o] = d_s1gh[o0+o]; c1v[o] = d_c1gh[o0+o];
        pw0[o] = w2h[o0+o]; pw1[o] = w2h[256+o0+o]; pw2[o] = w2h[512+o0+o];
    }
    const int lane = tid & 31, wid = tid >> 5;

#pragma unroll
    for (int pp = 0; pp < 8; pp++){
        float q0[2] = {0.f,0.f}, q1[2] = {0.f,0.f}, q2[2] = {0.f,0.f};
#pragma unroll
        for (int o = 0; o < 4; o++){
            float lo, hi; unpack2(acc2[o][pp], lo, hi);
            float h0 = fmaxf(lo*s1v[o] + c1v[o], 0.f);
            float h1 = fmaxf(hi*s1v[o] + c1v[o], 0.f);
            q0[0] += pw0[o]*h0; q1[0] += pw1[o]*h0; q2[0] += pw2[o]*h0;
            q0[1] += pw0[o]*h1; q1[1] += pw1[o]*h1; q2[1] += pw2[o]*h1;
        }
#pragma unroll
        for (int h = 0; h < 2; h++){
            float a = q0[h], c = q1[h], d = q2[h];
#pragma unroll
            for (int off = 16; off > 0; off >>= 1){
                a += __shfl_down_sync(0xffffffffu, a, off);
                c += __shfl_down_sync(0xffffffffu, c, off);
                d += __shfl_down_sync(0xffffffffu, d, off);
            }
            if (lane == 0){
                int p = p0 + 2*pp + h;
                part[0][p][wid & 1] = a;
                part[1][p][wid & 1] = c;
                part[2][p][wid & 1] = d;
            }
        }
    }
    __syncthreads();
    if (tid < 192){
        int j = tid >> 6, p = tid & 63;
        proj[j][p] = part[j][p][0] + part[j][p][1];
    }
    __syncthreads();
    if (tid < 64){
        int n = n0 + tid;
        if (n < NP){
            float g  = proj[2][tid] + b2h[2];
            float o0v = proj[0][tid] + b2h[0];
            float o1v = proj[1][tid] + b2h[1];
            bool obj = (o1v > o0v);
            size_t idx = (size_t)b * NP + n;
            d_graspness[idx] = g;
            out[OFF_GRASP + idx] = g;
            out[OFF_OBJ   + idx] = obj ? 1.f : 0.f;
            d_maskg[idx] = ((g > 0.1f) && obj) ? 1 : 0;
        }
    }
}

// =====================================================================
// Kernel 2: masked FPS (R12-proven).
// =====================================================================
#define CAP 12288
#define FPS_SMEM (CAP*8 + CAP*4 + CAP*2)

template<int KPT>
__device__ __forceinline__ void fps_smem_loop(
    const float2* __restrict__ sxy, const float* __restrict__ szz,
    const unsigned short* __restrict__ sidx, int M, int b,
    unsigned (&sval)[2][32], int (&sjj)[2][32],
    int tid, int lane, int wid)
{
    float dist[KPT];
#pragma unroll
    for (int k = 0; k < KPT; k++) dist[k] = 1e10f;

    int w = 0;
    int pb = 0;
    for (int it = 0; it < SS; it++){
        if (tid == 0) d_inds[b*SS + it] = (int)sidx[w];
        float2 cxy = sxy[w];
        float  cz  = szz[w];

        unsigned bvb = 0u; int bj = 0x7fffffff;
#pragma unroll
        for (int k = 0; k < KPT; k++){
            int j = tid + (k << 10);
            if (j < M){
                float2 p2 = sxy[j];
                float dx = p2.x - cxy.x, dy = p2.y - cxy.y, dz = szz[j] - cz;
                float d = fminf(dist[k], fmaf(dx, dx, fmaf(dy, dy, dz*dz)));
                dist[k] = d;
                unsigned db = __float_as_uint(d);
                if (db > bvb){ bvb = db; bj = j; }
            }
        }
        unsigned wm = __reduce_max_sync(0xffffffffu, bvb);
        unsigned cand = (bvb == wm) ? (unsigned)bj : 0x7fffffffu;
        cand = __reduce_min_sync(0xffffffffu, cand);
        if (lane == 0){ sval[pb][wid] = wm; sjj[pb][wid] = (int)cand; }
        __syncthreads();
        unsigned mv = sval[pb][lane];
        unsigned gm = __reduce_max_sync(0xffffffffu, mv);
        unsigned c2 = (mv == gm) ? (unsigned)sjj[pb][lane] : 0x7fffffffu;
        c2 = __reduce_min_sync(0xffffffffu, c2);
        w = (int)c2;
        pb ^= 1;
    }
}

__global__ __launch_bounds__(1024,1)
void fps_kernel(const float* __restrict__ xyz){
    extern __shared__ char smemc[];
    float2*          sxy  = (float2*)smemc;
    float*           szz  = (float*)(smemc + (size_t)CAP*8);
    unsigned short*  sidx = (unsigned short*)(smemc + (size_t)CAP*12);

    __shared__ unsigned sval[2][32];
    __shared__ int      sjj[2][32];
    __shared__ int      warp_i[32];
    __shared__ int scur;
    __shared__ int sM;

    const int b = blockIdx.x, tid = threadIdx.x;
    const int lane = tid & 31, wid = tid >> 5;
    const float* X = xyz + (size_t)b * NP * 3;
    const unsigned char* mk = d_maskg + (size_t)b * NP;

    int i0 = tid * 20;
    int cnt = 0;
    if (i0 < NP){
        int ie = min(i0 + 20, NP);
        for (int i = i0; i < ie; i++) cnt += mk[i] ? 1 : 0;
    }
    int x = cnt;
#pragma unroll
    for (int off = 1; off < 32; off <<= 1){
        int y = __shfl_up_sync(0xffffffffu, x, off);
        if (lane >= off) x += y;
    }
    if (lane == 31) warp_i[wid] = x;
    __syncthreads();
    if (wid == 0){
        int s = warp_i[lane];
#pragma unroll
        for (int off = 1; off < 32; off <<= 1){
            int y = __shfl_up_sync(0xffffffffu, s, off);
            if (lane >= off) s += y;
        }
        warp_i[lane] = s;
        if (lane == 31) sM = s;
    }
    __syncthreads();
    const int M = sM;
    int base = ((wid > 0) ? warp_i[wid-1] : 0) + (x - cnt);
    __syncthreads();

    if (M == 0){
        for (int it = tid; it < SS; it += 1024) d_inds[b*SS + it] = 0;
        return;
    }

    if (M <= CAP){
        if (i0 < NP){
            int ie = min(i0 + 20, NP);
            int p = base;
            for (int i = i0; i < ie; i++){
                if (mk[i]){
                    sxy[p] = make_float2(X[i*3+0], X[i*3+1]);
                    szz[p] = X[i*3+2];
                    sidx[p] = (unsigned short)i;
                    p++;
                }
            }
        }
        __syncthreads();

        int kmax = (M + 1023) >> 10;
        switch (kmax){
        case 1:  fps_smem_loop<1> (sxy,szz,sidx,M,b,sval,sjj,tid,lane,wid); break;
        case 2:  fps_smem_loop<2> (sxy,szz,sidx,M,b,sval,sjj,tid,lane,wid); break;
        case 3:  fps_smem_loop<3> (sxy,szz,sidx,M,b,sval,sjj,tid,lane,wid); break;
        case 4:  fps_smem_loop<4> (sxy,szz,sidx,M,b,sval,sjj,tid,lane,wid); break;
        case 5:  fps_smem_loop<5> (sxy,szz,sidx,M,b,sval,sjj,tid,lane,wid); break;
        case 6:  fps_smem_loop<6> (sxy,szz,sidx,M,b,sval,sjj,tid,lane,wid); break;
        case 7:  fps_smem_loop<7> (sxy,szz,sidx,M,b,sval,sjj,tid,lane,wid); break;
        case 8:  fps_smem_loop<8> (sxy,szz,sidx,M,b,sval,sjj,tid,lane,wid); break;
        case 9:  fps_smem_loop<9> (sxy,szz,sidx,M,b,sval,sjj,tid,lane,wid); break;
        case 10: fps_smem_loop<10>(sxy,szz,sidx,M,b,sval,sjj,tid,lane,wid); break;
        case 11: fps_smem_loop<11>(sxy,szz,sidx,M,b,sval,sjj,tid,lane,wid); break;
        default: fps_smem_loop<12>(sxy,szz,sidx,M,b,sval,sjj,tid,lane,wid); break;
        }
    } else {
        float* fd = d_fdist + (size_t)b * NP;
        int startv = 0x7fffffff;
        for (int i = tid; i < NP; i += 1024){
            bool m = mk[i] != 0;
            fd[i] = m ? 1e10f : -1.f;
            if (m) startv = min(startv, i);
        }
        startv = (int)__reduce_min_sync(0xffffffffu, (unsigned)startv);
        if (lane == 0) warp_i[wid] = startv;
        __syncthreads();
        if (wid == 0){
            int s = (int)__reduce_min_sync(0xffffffffu, (unsigned)warp_i[lane]);
            if (lane == 0) scur = s;
        }
        __syncthreads();
        int cur = scur;
        __syncthreads();

        int pb = 0;
        for (int it = 0; it < SS; it++){
            if (tid == 0) d_inds[b*SS + it] = cur;
            float cx = X[cur*3+0], cy = X[cur*3+1], cz = X[cur*3+2];
            unsigned bvb = 0u; int bi = 0x7fffffff;
            for (int i = tid; i < NP; i += 1024){
                float d = fd[i];
                if (d >= 0.f){
                    float dx = X[i*3+0]-cx, dy = X[i*3+1]-cy, dz = X[i*3+2]-cz;
                    d = fminf(d, fmaf(dx,dx, fmaf(dy,dy, dz*dz)));
                    fd[i] = d;
                    unsigned db = __float_as_uint(d);
                    if (db > bvb || bi == 0x7fffffff){ bvb = db; bi = i; }
                }
            }
            unsigned wm = __reduce_max_sync(0xffffffffu, bvb);
            unsigned cand = (bvb == wm) ? (unsigned)bi : 0x7fffffffu;
            cand = __reduce_min_sync(0xffffffffu, cand);
            if (lane == 0){ sval[pb][wid] = wm; sjj[pb][wid] = (int)cand; }
            __syncthreads();
            unsigned mv = sval[pb][lane];
            unsigned gm = __reduce_max_sync(0xffffffffu, mv);
            unsigned c2 = (mv == gm) ? (unsigned)sjj[pb][lane] : 0x7fffffffu;
            c2 = __reduce_min_sync(0xffffffffu, c2);
            cur = (int)c2;
            pb ^= 1;
        }
    }
}

// =====================================================================
// FUSED 3-layer MLP over 1024 samples. grid (32, BB), 320 threads.
// Per block: gather in0[256][32] -> L0 -> h1[256][32] -> L1 ->
// h2 (aliased over in0) -> L2 -> view_score. Thread tile 4 outs x 8 pts.
// Weights streamed from global (L2-hot), f32x2 math.
// =====================================================================
#define MLP_SMEM ((9728 + 8192) * 4)

__global__ __launch_bounds__(320)
void mlp_fused(const float* __restrict__ F, const float* __restrict__ b3,
               float* __restrict__ out){
    extern __shared__ float sm[];
    float* bufA = sm;            // in0 [256][32] (8192) then h2 [<=304][32]
    float* h1   = sm + 9728;     // [256][32]
    __shared__ int sidxs[32];

    const int tid = threadIdx.x;
    const int b   = blockIdx.y;
    const int s0t = blockIdx.x * 32;
    const int sg  = tid / 80;          // 0..3  (8-sample group)
    const int og  = tid - sg * 80;     // 0..79 (4-out group)
    const int o0  = og * 4;
    const int sb  = sg * 8;

    if (tid < 32) sidxs[tid] = d_inds[b*SS + s0t + tid];
    __syncthreads();

    // gather input features (one-time, scattered)
    const float* Fb = F + (size_t)b * CC * NP;
    for (int e = tid; e < CC*32; e += 320){
        int k = e >> 5, t = e & 31;
        bufA[e] = Fb[(size_t)k * NP + sidxs[t]];
    }
    __syncthreads();

    unsigned long long acc[4][4];

    // ---------- layer 0: K=256, O=256 (og<64 active) ----------
#pragma unroll
    for (int o = 0; o < 4; o++)
#pragma unroll
        for (int i = 0; i < 4; i++) acc[o][i] = 0ULL;
    if (og < 64){
        for (int k = 0; k < CC; k++){
            float4 w4 = *(const float4*)(d_w1T + (size_t)k*CC + o0);
            const ulonglong2* fr = (const ulonglong2*)(bufA + k*32 + sb);
            ulonglong2 fa = fr[0], fb = fr[1];
            unsigned long long fv0 = fa.x, fv1 = fa.y, fv2 = fb.x, fv3 = fb.y;
            unsigned long long wa = pack2(w4.x), wb = pack2(w4.y),
                               wc = pack2(w4.z), wd = pack2(w4.w);
            FMA2(acc[0][0], fv0, wa); FMA2(acc[0][1], fv1, wa);
            FMA2(acc[0][2], fv2, wa); FMA2(acc[0][3], fv3, wa);
            FMA2(acc[1][0], fv0, wb); FMA2(acc[1][1], fv1, wb);
            FMA2(acc[1][2], fv2, wb); FMA2(acc[1][3], fv3, wb);
            FMA2(acc[2][0], fv0, wc); FMA2(acc[2][1], fv1, wc);
            FMA2(acc[2][2], fv2, wc); FMA2(acc[2][3], fv3, wc);
            FMA2(acc[3][0], fv0, wd); FMA2(acc[3][1], fv1, wd);
            FMA2(acc[3][2], fv2, wd); FMA2(acc[3][3], fv3, wd);
        }
    }
    __syncthreads();   // all in0 reads complete
    if (og < 64){
#pragma unroll
        for (int o = 0; o < 4; o++){
            float sc = d_sA[o0+o], sh = d_cA[o0+o];
            float* row = h1 + (o0+o)*32 + sb;
#pragma unroll
            for (int i = 0; i < 4; i++){
                float lo, hi; unpack2(acc[o][i], lo, hi);
                row[2*i]   = fmaxf(lo*sc + sh, 0.f);
                row[2*i+1] = fmaxf(hi*sc + sh, 0.f);
            }
        }
    }
    __syncthreads();

    // ---------- layer 1: K=256, O=320 (all threads) ----------
#pragma unroll
    for (int o = 0; o < 4; o++)
#pragma unroll
        for (int i = 0; i < 4; i++) acc[o][i] = 0ULL;
    for (int k = 0; k < CC; k++){
        float4 w4 = *(const float4*)(d_w2T + (size_t)k*OPAD + o0);
        const ulonglong2* fr = (const ulonglong2*)(h1 + k*32 + sb);
        ulonglong2 fa = fr[0], fb = fr[1];
        unsigned long long fv0 = fa.x, fv1 = fa.y, fv2 = fb.x, fv3 = fb.y;
        unsigned long long wa = pack2(w4.x), wb = pack2(w4.y),
                           wc = pack2(w4.z), wd = pack2(w4.w);
        FMA2(acc[0][0], fv0, wa); FMA2(acc[0][1], fv1, wa);
        FMA2(acc[0][2], fv2, wa); FMA2(acc[0][3], fv3, wa);
        FMA2(acc[1][0], fv0, wb); FMA2(acc[1][1], fv1, wb);
        FMA2(acc[1][2], fv2, wb); FMA2(acc[1][3], fv3, wb);
        FMA2(acc[2][0], fv0, wc); FMA2(acc[2][1], fv1, wc);
        FMA2(acc[2][2], fv2, wc); FMA2(acc[2][3], fv3, wc);
        FMA2(acc[3][0], fv0, wd); FMA2(acc[3][1], fv1, wd);
        FMA2(acc[3][2], fv2, wd); FMA2(acc[3][3], fv3, wd);
    }
    if (og < 75){   // outs o0..o0+3 <= 299
#pragma unroll
        for (int o = 0; o < 4; o++){
            int oo = o0 + o;
            float sc = d_sB[oo], sh = d_cB[oo];
            float* row = bufA + oo*32 + sb;   // h2 (in0 is dead)
#pragma unroll
            for (int i = 0; i < 4; i++){
                float lo, hi; unpack2(acc[o][i], lo, hi);
                row[2*i]   = fmaxf(lo*sc + sh, 0.f);
                row[2*i+1] = fmaxf(hi*sc + sh, 0.f);
            }
        }
    }
    __syncthreads();

    // ---------- layer 2: K=300, O=300 ----------
#pragma unroll
    for (int o = 0; o < 4; o++)
#pragma unroll
        for (int i = 0; i < 4; i++) acc[o][i] = 0ULL;
    for (int k = 0; k < VV; k++){
        float4 w4 = *(const float4*)(d_w3T + (size_t)k*OPAD + o0);
        const ulonglong2* fr = (const ulonglong2*)(bufA + k*32 + sb);
        ulonglong2 fa = fr[0], fb = fr[1];
        unsigned long long fv0 = fa.x, fv1 = fa.y, fv2 = fb.x, fv3 = fb.y;
        unsigned long long wa = pack2(w4.x), wb = pack2(w4.y),
                           wc = pack2(w4.z), wd = pack2(w4.w);
        FMA2(acc[0][0], fv0, wa); FMA2(acc[0][1], fv1, wa);
        FMA2(acc[0][2], fv2, wa); FMA2(acc[0][3], fv3, wa);
        FMA2(acc[1][0], fv0, wb); FMA2(acc[1][1], fv1, wb);
        FMA2(acc[1][2], fv2, wb); FMA2(acc[1][3], fv3, wb);
        FMA2(acc[2][0], fv0, wc); FMA2(acc[2][1], fv1, wc);
        FMA2(acc[2][2], fv2, wc); FMA2(acc[2][3], fv3, wc);
        FMA2(acc[3][0], fv0, wd); FMA2(acc[3][1], fv1, wd);
        FMA2(acc[3][2], fv2, wd); FMA2(acc[3][3], fv3, wd);
    }
    if (og < 75){
        float b0 = b3[o0], b1v = b3[o0+1], b2v = b3[o0+2], b3v = b3[o0+3];
#pragma unroll
        for (int i = 0; i < 4; i++){
            float l0,h0v,l1,h1v,l2,h2v,l3,h3v;
            unpack2(acc[0][i], l0, h0v);
            unpack2(acc[1][i], l1, h1v);
            unpack2(acc[2][i], l2, h2v);
            unpack2(acc[3][i], l3, h3v);
            int s = s0t + sb + 2*i;
            float4 va = make_float4(l0+b0, l1+b1v, l2+b2v, l3+b3v);
            float4 vb = make_float4(h0v+b0, h1v+b1v, h2v+b2v, h3v+b3v);
            *(float4*)(out + OFF_VS + ((size_t)(b*SS + s))*VV + o0) = va;
            *(float4*)(out + OFF_VS + ((size_t)(b*SS + s + 1))*VV + o0) = vb;
        }
    }
}

// =====================================================================
// gathers (output copies only)
// =====================================================================
__global__ void gather_small(const float* __restrict__ xyz, float* __restrict__ out){
    int g = blockIdx.x * blockDim.x + threadIdx.x;
    if (g >= BB*SS) return;
    int b = g >> 10;
    int idx = d_inds[g];
    out[OFF_INDS + g] = (float)idx;
    size_t p = (size_t)b * NP + idx;
    out[OFF_GXYZ + (size_t)g*3 + 0] = xyz[p*3 + 0];
    out[OFF_GXYZ + (size_t)g*3 + 1] = xyz[p*3 + 1];
    out[OFF_GXYZ + (size_t)g*3 + 2] = xyz[p*3 + 2];
    out[OFF_FP2 + g] = d_graspness[p];
}

__global__ void gather_feat_out(const float* __restrict__ F, float* __restrict__ out){
    int b = blockIdx.x, c = blockIdx.y, tid = threadIdx.x;
    const float* Fr = F + ((size_t)b*CC + c) * NP;
    float* g2p = out + OFF_GFEAT + ((size_t)b*CC + c) * SS;
#pragma unroll
    for (int r = 0; r < 4; r++){
        int s = r*256 + tid;
        int idx = d_inds[b*SS + s];
        g2p[s] = Fr[idx];
    }
}

// =====================================================================
// top view + rotation epilogue
// =====================================================================
__global__ void top_kernel(float* __restrict__ out){
    int g = blockIdx.x * blockDim.x + threadIdx.x;
    if (g >= BB*SS) return;
    const float* row = out + OFF_VS + (size_t)g * VV;
    float bv = row[0]; int bi = 0;
    for (int o = 1; o < VV; o++){
        float v = row[o];
        if (v > bv){ bv = v; bi = o; }
    }
    out[OFF_TVI + g] = (float)bi;
    out[OFF_TVS + g] = bv;
    float tx = d_tpl[bi*3+0], ty = d_tpl[bi*3+1], tz = d_tpl[bi*3+2];
    out[OFF_VPX + (size_t)g*3 + 0] = tx;
    out[OFF_VPX + (size_t)g*3 + 1] = ty;
    out[OFF_VPX + (size_t)g*3 + 2] = tz;

    float ax = -tx, ay = -ty, az = -tz;
    float byx = -ay, byy = ax, byz = 0.f;
    float ny = sqrtf(byx*byx + byy*byy);
    if (ny == 0.f){ byx = 0.f; byy = 1.f; byz = 0.f; }
    float nx = sqrtf(ax*ax + ay*ay + az*az);
    ax /= nx; ay /= nx; az /= nx;
    float ny2 = sqrtf(byx*byx + byy*byy + byz*byz);
    byx /= ny2; byy /= ny2; byz /= ny2;
    float czx = ay*byz - az*byy;
    float czy = az*byx - ax*byz;
    float czz = ax*byy - ay*byx;
    float* R = out + OFF_ROT + (size_t)g * 9;
    R[0] = ax; R[1] = byx; R[2] = czx;
    R[3] = ay; R[4] = byy; R[5] = czy;
    R[6] = az; R[7] = byz; R[8] = czz;
}

// =====================================================================
extern "C" void kernel_launch(void* const* d_in, const int* in_sizes, int n_in,
                              void* d_out, int out_size){
    const float* seed_xyz  = (const float*)d_in[0];
    const float* seed_feat = (const float*)d_in[1];
    const float* gh_w1 = (const float*)d_in[2];
    const float* gh_b1 = (const float*)d_in[3];
    const float* gh_g1 = (const float*)d_in[4];
    const float* gh_be1= (const float*)d_in[5];
    const float* gh_m1 = (const float*)d_in[6];
    const float* gh_v1 = (const float*)d_in[7];
    const float* gh_w2 = (const float*)d_in[8];
    const float* gh_b2 = (const float*)d_in[9];
    const float* w1  = (const float*)d_in[10];
    const float* b1  = (const float*)d_in[11];
    const float* g1  = (const float*)d_in[12];
    const float* be1 = (const float*)d_in[13];
    const float* m1  = (const float*)d_in[14];
    const float* v1  = (const float*)d_in[15];
    const float* w2  = (const float*)d_in[16];
    const float* b2  = (const float*)d_in[17];
    const float* g2  = (const float*)d_in[18];
    const float* be2 = (const float*)d_in[19];
    const float* m2  = (const float*)d_in[20];
    const float* v2  = (const float*)d_in[21];
    const float* w3  = (const float*)d_in[22];
    const float* b3  = (const float*)d_in[23];
    float* out = (float*)d_out;

    static bool attr_set = false;
    if (!attr_set){
        cudaFuncSetAttribute(fps_kernel, cudaFuncAttributeMaxDynamicSharedMemorySize, FPS_SMEM);
        cudaFuncSetAttribute(mlp_fused, cudaFuncAttributeMaxDynamicSharedMemorySize, MLP_SMEM);
        attr_set = true;
    }

    const int total_tr = CC*CC + CC*CC + CC*OPAD + VV*OPAD;
    // position 1
    prep_all<<<1 + (total_tr + 255)/256, 256>>>(gh_w1, w1, w2, w3,
                            gh_b1, gh_g1, gh_be1, gh_m1, gh_v1,
                            b1, g1, be1, m1, v1,
                            b2, g2, be2, m2, v2);
    // position 2
    k1_head<<<dim3((NP + 63)/64, BB), 256>>>(seed_feat, gh_w2, gh_b2, out);
    // position 3
    fps_kernel<<<BB, 1024, FPS_SMEM>>>(seed_xyz);
    // position 4 (PROFILED): fused 3-layer MLP
    mlp_fused<<<dim3(SS/32, BB), 320, MLP_SMEM>>>(seed_feat, b3, out);

    gather_small<<<(BB*SS + 255)/256, 256>>>(seed_xyz, out);
    gather_feat_out<<<dim3(BB, CC), 256>>>(seed_feat, out);

    top_kernel<<<(BB*SS + 255)/256, 256>>>(out);
}